// round 9
// baseline (speedup 1.0000x reference)
#include <cuda_runtime.h>
#include <math.h>

// ---------------- static config ----------------
static constexpr int NB = 8;
static constexpr int ND = 256;
static constexpr int NC = 64;
static constexpr int NHID = 128;
static constexpr int NS = 64;
static constexpr int NHH = 28, NWW = 28;
static constexpr int NL = NHH * NWW;        // 784
static constexpr int NHEAD = 16;
static constexpr int NPAIRS = NB * NL / 2;  // 3136
static constexpr int PPB = NL / 2;          // 392

// ---------------- scratch arena ----------------
static constexpr long O_X1O   = 0;                          // (8,64,784)
static constexpr long O_T2    = O_X1O   + (long)NB*NC*NL;   // (8,128,784)
static constexpr long O_TMP1  = O_T2    + (long)NB*NHID*NL; // (8,64,784)
static constexpr long O_BCDT0 = O_TMP1  + (long)NB*NC*NL;   // (8,192,784)
static constexpr long O_CM    = O_BCDT0 + (long)NB*192*NL;  // (8,64,784)
static constexpr long O_H     = O_CM    + (long)NB*NC*NL;   // (8,64,64)
static constexpr long O_U     = O_H     + (long)NB*NC*NS;   // (8,64,64)
static constexpr long O_QKV   = O_U     + (long)NB*NC*NS;   // (8,192,784)
static constexpr long O_O     = O_QKV   + (long)NB*192*NL;  // (8,64,784)
static constexpr long O_XA    = O_O     + (long)NB*NC*NL;   // (8,256,784)
static constexpr long O_M1    = O_XA    + (long)NB*ND*NL;   // (8,128,784)
static constexpr long SCR_TOTAL = O_M1 + (long)NB*NHID*NL;

__device__ __align__(16) float g_scr[SCR_TOTAL];

enum { M_NONE = 0, M_ADD_BN, M_BN_RELU, M_BN_ADD, M_BN };

struct MegaParams {
    const float *x, *dw1_w, *dw1_b, *bn_dw1, *f1_w, *f1_b, *f2_w, *f2_b,
                *g_w, *g_b, *bn_g, *dw2_w, *dw2_b,
                *h1w, *v1w, *h2w, *v2w, *bn_mra,
                *bcdt_w, *ssd_dw, *hz_w, *ow, *A, *D,
                *qkv_w, *proj_w, *bn_n4, *mlp1_w, *bn_mlp, *mlp2_w, *bn_n1;
    float* out;
};

// ---------------- unit: pointwise conv (16 outputs x 256 pixel-pairs) ----------------
template <int CIN>
__device__ void pw_unit(float* sm, int otile, int pslot,
                        const float* __restrict__ in, long ibs,
                        const float* __restrict__ w, int cout,
                        const float* __restrict__ bias, const float* __restrict__ bnp,
                        const float* __restrict__ res, long rbs,
                        float* __restrict__ out, long obs, int mode) {
    float* ws = sm;  // transposed: ws[c*16+i]
    int obase = otile * 16;
    for (int idx = threadIdx.x; idx < CIN * 16; idx += 256) {
        int c = idx >> 4, i = idx & 15;
        ws[idx] = w[(long)(obase + i) * CIN + c];
    }
    __syncthreads();
    int pp = pslot * 256 + threadIdx.x;
    if (pp >= NPAIRS) return;
    int b = pp / PPB;
    int l = (pp % PPB) * 2;
    const float2* ip2 = reinterpret_cast<const float2*>(in + (long)b * ibs + l);
    float a0[16], a1[16];
#pragma unroll
    for (int i = 0; i < 16; i++) { a0[i] = 0.f; a1[i] = 0.f; }
#pragma unroll 4
    for (int c = 0; c < CIN; c++) {
        float2 xv = ip2[c * (NL / 2)];
        const float* wc = ws + c * 16;
#pragma unroll
        for (int i = 0; i < 16; i++) {
            float wv = wc[i];
            a0[i] += wv * xv.x;
            a1[i] += wv * xv.y;
        }
    }
#pragma unroll
    for (int i = 0; i < 16; i++) {
        int o = obase + i;
        float s0 = a0[i], s1 = a1[i];
        if (bias) { s0 += bias[o]; s1 += bias[o]; }
        if (mode >= M_ADD_BN) {
            long roff = (long)b * rbs + (long)o * NL + l;
            if (mode == M_ADD_BN) {
                float2 rv = *reinterpret_cast<const float2*>(res + roff);
                s0 += rv.x; s1 += rv.y;
            }
            float g = bnp[o], be = bnp[cout + o], mm = bnp[2 * cout + o],
                  vv = bnp[3 * cout + o];
            float sc = g * rsqrtf(vv + 1e-5f);
            s0 = (s0 - mm) * sc + be;
            s1 = (s1 - mm) * sc + be;
            if (mode == M_BN_RELU) { s0 = fmaxf(s0, 0.f); s1 = fmaxf(s1, 0.f); }
            if (mode == M_BN_ADD) {
                float2 rv = *reinterpret_cast<const float2*>(res + roff);
                s0 += rv.x; s1 += rv.y;
            }
        }
        *reinterpret_cast<float2*>(out + (long)b * obs + (long)o * NL + l) =
            make_float2(s0, s1);
    }
}

// ---------------- unit: star MLP ----------------
__device__ void star_unit(float* sm, int otile, int pslot,
                          const float* __restrict__ in,
                          const float* __restrict__ w1, const float* __restrict__ b1,
                          const float* __restrict__ w2, const float* __restrict__ b2,
                          float* __restrict__ out) {
    float* ws1 = sm;
    float* ws2 = sm + NC * 16;
    int obase = otile * 16;
    for (int idx = threadIdx.x; idx < NC * 16; idx += 256) {
        int c = idx >> 4, i = idx & 15;
        ws1[idx] = w1[(long)(obase + i) * NC + c];
        ws2[idx] = w2[(long)(obase + i) * NC + c];
    }
    __syncthreads();
    int pp = pslot * 256 + threadIdx.x;
    if (pp >= NPAIRS) return;
    int b = pp / PPB;
    int l = (pp % PPB) * 2;
    const float2* ip2 = reinterpret_cast<const float2*>(in + (long)b * NC * NL + l);
    float p0[16], p1[16], q0[16], q1[16];
#pragma unroll
    for (int i = 0; i < 16; i++) { p0[i] = p1[i] = q0[i] = q1[i] = 0.f; }
#pragma unroll 4
    for (int c = 0; c < NC; c++) {
        float2 xv = ip2[c * (NL / 2)];
        const float* w1c = ws1 + c * 16;
        const float* w2c = ws2 + c * 16;
#pragma unroll
        for (int i = 0; i < 16; i++) {
            p0[i] += w1c[i] * xv.x; p1[i] += w1c[i] * xv.y;
            q0[i] += w2c[i] * xv.x; q1[i] += w2c[i] * xv.y;
        }
    }
#pragma unroll
    for (int i = 0; i < 16; i++) {
        int o = obase + i;
        float h0 = fminf(fmaxf(p0[i] + b1[o], 0.f), 6.f);
        float h1 = fminf(fmaxf(p1[i] + b1[o], 0.f), 6.f);
        *reinterpret_cast<float2*>(out + ((long)b * NHID + o) * NL + l) =
            make_float2(h0 * (q0[i] + b2[o]), h1 * (q1[i] + b2[o]));
    }
}

// ---------------- unit: depthwise 7x7 ----------------
__device__ void dw7_unit(float* sm, int u, const float* __restrict__ in, long ibs,
                         const float* __restrict__ w, const float* __restrict__ bias,
                         const float* __restrict__ bnp,
                         float* __restrict__ out, long obs) {
    float* pl = sm;          // 34x34
    float* wsh = sm + 1156;  // 49
    int c = u & 63, b = u >> 6;
    const float* ip = in + (long)b * ibs + (long)c * NL;
    int t = threadIdx.x;
    for (int i = t; i < 1156; i += 256) pl[i] = 0.f;
    if (t < 49) wsh[t] = w[c * 49 + t];
    __syncthreads();
    for (int i = t; i < NL; i += 256) {
        int y = i / NWW, x = i % NWW;
        pl[(y + 3) * 34 + x + 3] = ip[i];
    }
    __syncthreads();
    float sc = 1.f, sh = 0.f;
    if (bnp) {
        float g = bnp[c], be = bnp[NC + c], mm = bnp[2 * NC + c], vv = bnp[3 * NC + c];
        sc = g * rsqrtf(vv + 1e-5f);
        sh = be - mm * sc;
    }
    float bi = bias[c];
    for (int i = t; i < NL; i += 256) {
        int y = i / NWW, x = i % NWW;
        float s = 0.f;
#pragma unroll
        for (int ky = 0; ky < 7; ky++)
#pragma unroll
            for (int kx = 0; kx < 7; kx++)
                s += wsh[ky * 7 + kx] * pl[(y + ky) * 34 + x + kx];
        out[(long)b * obs + (long)c * NL + i] = (s + bi) * sc + sh;
    }
}

// ---------------- unit: dw3x3 of Cm -> cmbuf ----------------
__device__ void cm_unit(float* sm, int u, const float* __restrict__ bcdt0,
                        const float* __restrict__ dw, float* __restrict__ cmbuf) {
    float* pl = sm;         // 30x30
    float* wsh = sm + 900;  // 9
    int s = u & 63, b = u >> 6;
    const float* ip = bcdt0 + ((long)b * 192 + 64 + s) * NL;
    int t = threadIdx.x;
    for (int i = t; i < 900; i += 256) pl[i] = 0.f;
    if (t < 9) wsh[t] = dw[(64 + s) * 9 + t];
    __syncthreads();
    for (int i = t; i < NL; i += 256) {
        int y = i / NWW, x = i % NWW;
        pl[(y + 1) * 30 + x + 1] = ip[i];
    }
    __syncthreads();
    for (int i = t; i < NL; i += 256) {
        int y = i / NWW, x = i % NWW;
        float v = 0.f;
#pragma unroll
        for (int ky = 0; ky < 3; ky++)
#pragma unroll
            for (int kx = 0; kx < 3; kx++)
                v += wsh[ky * 3 + kx] * pl[(y + ky) * 30 + x + kx];
        cmbuf[((long)b * NC + s) * NL + i] = v;
    }
}

// ---------------- unit: branch 2 MRA ----------------
__device__ void mra_unit(float* sm, int u, const float* __restrict__ x,
                         const float* __restrict__ h1w, const float* __restrict__ v1w,
                         const float* __restrict__ h2w, const float* __restrict__ v2w,
                         const float* __restrict__ bnp, float* __restrict__ xa) {
    float* xp = sm;            // 784
    float* mp = sm + 784;      // 784
    float* xs = mp + 784;      // 100
    float* ht = xs + 100;      // 190
    float* vt = ht + 190;      // 190
    float* c2 = vt + 190;      // 190
    float* c2v = c2 + 190;     // 190
    float* att_s = c2v + 190;  // 100
    int c = u & 63, b = u >> 6;
    const float* ip = x + ((long)b * ND + NC + c) * NL;
    int t = threadIdx.x;
    for (int i = t; i < NL; i += 256) xp[i] = ip[i];
    __syncthreads();
    for (int i = t; i < NL; i += 256) {
        int y = i / NWW, xx = i % NWW;
        float mx = -1e30f;
        for (int dy = -1; dy <= 1; dy++) {
            int yy = y + dy;
            if (yy < 0 || yy >= NHH) continue;
            for (int dx = -1; dx <= 1; dx++) {
                int xxx = xx + dx;
                if (xxx < 0 || xxx >= NWW) continue;
                mx = fmaxf(mx, xp[yy * NWW + xxx]);
            }
        }
        mp[i] = mx;
    }
    __syncthreads();
    if (t < 100) {
        int i = t / 10, j = t % 10;
        const float filt[4] = {1.f, 3.f, 3.f, 1.f};
        float s = 0.f;
        for (int fy = 0; fy < 4; fy++) {
            int oy = 3 * i + fy - 1;
            if (oy < 0) oy = -oy;
            if (oy >= NHH) oy = 2 * NHH - 2 - oy;
            for (int fx = 0; fx < 4; fx++) {
                int ox = 3 * j + fx - 1;
                if (ox < 0) ox = -ox;
                if (ox >= NWW) ox = 2 * NWW - 2 - ox;
                s += filt[fy] * filt[fx] * mp[oy * NWW + ox];
            }
        }
        xs[t] = s * (1.f / 64.f);
    }
    __syncthreads();
    if (t < 190) {
        {
            int row = t / 20, col = t % 20;
            ht[t] = (col < 10) ? xs[row * 10 + col] : 0.f;
        }
        {
            int a = t / 10, b2 = t % 10;
            int k = b2 * 19 + a, row = k / 20, col = k % 20;
            vt[t] = (col < 10) ? xs[col * 10 + row] : 0.f;
        }
    }
    __syncthreads();
    if (t < 190) {
        {
            int r = t / 19, j = t % 19;
            float s = 0.f;
            for (int ky = 0; ky < 11; ky++) {
                int yy = r + ky - 5;
                if (yy < 0 || yy >= 10) continue;
                for (int kx = 0; kx < 3; kx++) {
                    int xx = j + kx - 1;
                    if (xx < 0 || xx >= 19) continue;
                    s += h2w[c * 33 + ky * 3 + kx] * ht[yy * 19 + xx];
                }
            }
            c2[t] = s;
        }
        {
            int y = t / 10, x2 = t % 10;
            float s = 0.f;
            for (int ky = 0; ky < 3; ky++) {
                int yy = y + ky - 1;
                if (yy < 0 || yy >= 19) continue;
                for (int kx = 0; kx < 11; kx++) {
                    int xx = x2 + kx - 5;
                    if (xx < 0 || xx >= 10) continue;
                    s += v2w[c * 33 + ky * 11 + kx] * vt[yy * 10 + xx];
                }
            }
            c2v[t] = s;
        }
    }
    __syncthreads();
    if (t < 100) {
        int y = t / 10, xx = t % 10;
        float s = 0.f;
        for (int ky = 0; ky < 11; ky++) {
            int yy = y + ky - 5;
            if (yy < 0 || yy >= 10) continue;
            for (int kx = 0; kx < 3; kx++) {
                int xxx = xx + kx - 1;
                if (xxx < 0 || xxx >= 10) continue;
                s += h1w[c * 33 + ky * 3 + kx] * xs[yy * 10 + xxx];
            }
        }
        for (int ky = 0; ky < 3; ky++) {
            int yy = y + ky - 1;
            if (yy < 0 || yy >= 10) continue;
            for (int kx = 0; kx < 11; kx++) {
                int xxx = xx + kx - 5;
                if (xxx < 0 || xxx >= 10) continue;
                s += v1w[c * 33 + ky * 11 + kx] * xs[yy * 10 + xxx];
            }
        }
        s += c2[y * 20 + xx];
        int k4 = xx * 20 + y;
        s += c2v[(k4 % 19) * 10 + (k4 / 19)];
        float g = bnp[c], be = bnp[NC + c], mm = bnp[2 * NC + c], vv = bnp[3 * NC + c];
        float sc = g * rsqrtf(vv + 1e-5f);
        s = (s - mm) * sc + be;
        att_s[t] = 1.f / (1.f + __expf(-s));
    }
    __syncthreads();
    float* op = xa + (long)b * ND * NL + (long)(NC + c) * NL;
    for (int i = t; i < NL; i += 256) {
        int y = i / NWW, xx = i % NWW;
        op[i] = xp[i] * att_s[((y * 10) / NHH) * 10 + (xx * 10) / NWW];
    }
}

// ---------------- unit: SSD W (conv+softmax) + h-GEMM ----------------
__device__ void wh_unit(float* sm, int u, const float* __restrict__ x,
                        const float* __restrict__ bcdt0, const float* __restrict__ dw,
                        const float* __restrict__ A_param, float* __restrict__ h) {
    float* Wsh = sm;  // 8 x 784
    int stile = u & 7, b = u >> 3;
    int warp = threadIdx.x / 32, lane = threadIdx.x % 32;
    {
        int s = stile * 8 + warp;
        float wd[9], wb[9];
#pragma unroll
        for (int k = 0; k < 9; k++) {
            wd[k] = dw[(128 + s) * 9 + k];
            wb[k] = dw[s * 9 + k];
        }
        const float* dtp = bcdt0 + ((long)b * 192 + 128 + s) * NL;
        const float* bmp = bcdt0 + ((long)b * 192 + s) * NL;
        float ap = A_param[s];
        float mx = -1e30f;
        for (int l = lane; l < NL; l += 32) {
            int y = l / NWW, xx = l % NWW;
            float v = 0.f;
#pragma unroll
            for (int ky = 0; ky < 3; ky++) {
                int yy = y + ky - 1;
                if (yy < 0 || yy >= NHH) continue;
#pragma unroll
                for (int kx = 0; kx < 3; kx++) {
                    int xxx = xx + kx - 1;
                    if (xxx < 0 || xxx >= NWW) continue;
                    v += wd[ky * 3 + kx] * dtp[yy * NWW + xxx];
                }
            }
            v += ap;
            Wsh[warp * NL + l] = v;
            mx = fmaxf(mx, v);
        }
#pragma unroll
        for (int o = 16; o > 0; o >>= 1)
            mx = fmaxf(mx, __shfl_xor_sync(0xffffffff, mx, o));
        float sum = 0.f;
        for (int l = lane; l < NL; l += 32) {
            float e = __expf(Wsh[warp * NL + l] - mx);
            Wsh[warp * NL + l] = e;
            sum += e;
        }
#pragma unroll
        for (int o = 16; o > 0; o >>= 1)
            sum += __shfl_xor_sync(0xffffffff, sum, o);
        float inv = 1.f / sum;
        for (int l = lane; l < NL; l += 32) {
            int y = l / NWW, xx = l % NWW;
            float v = 0.f;
#pragma unroll
            for (int ky = 0; ky < 3; ky++) {
                int yy = y + ky - 1;
                if (yy < 0 || yy >= NHH) continue;
#pragma unroll
                for (int kx = 0; kx < 3; kx++) {
                    int xxx = xx + kx - 1;
                    if (xxx < 0 || xxx >= NWW) continue;
                    v += wb[ky * 3 + kx] * bmp[yy * NWW + xxx];
                }
            }
            Wsh[warp * NL + l] *= inv * v;
        }
    }
    __syncthreads();
    for (int i = 0; i < 8; i++) {
        int c = i * 8 + warp;
        const float* xsrc = x + ((long)b * ND + 128 + c) * NL;
        float acc[8];
#pragma unroll
        for (int k = 0; k < 8; k++) acc[k] = 0.f;
        for (int l = lane; l < NL; l += 32) {
            float xv = xsrc[l];
#pragma unroll
            for (int k = 0; k < 8; k++) acc[k] += xv * Wsh[k * NL + l];
        }
#pragma unroll
        for (int k = 0; k < 8; k++) {
#pragma unroll
            for (int o = 16; o > 0; o >>= 1)
                acc[k] += __shfl_down_sync(0xffffffff, acc[k], o);
        }
        if (lane == 0) {
#pragma unroll
            for (int k = 0; k < 8; k++)
                h[((long)b * NC + c) * NS + stile * 8 + k] = acc[k];
        }
    }
}

// ---------------- unit: attention (256 rows) ----------------
__device__ void attn_unit(float* sm, int u, const float* __restrict__ qkv,
                          float* __restrict__ o) {
    float* Ks = sm;
    float* Vs = sm + NL * 4;
    int chunk = u & 3, bh = u >> 2;
    int head = bh % NHEAD, b = bh / NHEAD;
    const float* kbase = qkv + ((long)b * 192 + 64 + head * 4) * NL;
    const float* vbase = qkv + ((long)b * 192 + 128 + head * 4) * NL;
    for (int i = threadIdx.x; i < NL * 4; i += 256) {
        int d = i / NL, l = i % NL;
        Ks[l * 4 + d] = kbase[i];
        Vs[l * 4 + d] = vbase[i];
    }
    __syncthreads();
    int row = chunk * 256 + threadIdx.x;
    if (row >= NL) return;
    const float* qb = qkv + ((long)b * 192 + head * 4) * NL;
    float q0 = qb[row] * 0.5f, q1 = qb[NL + row] * 0.5f;
    float q2 = qb[2 * NL + row] * 0.5f, q3 = qb[3 * NL + row] * 0.5f;
    float se = 0.f, a0 = 0.f, a1 = 0.f, a2 = 0.f, a3 = 0.f;
    const float4* K4 = reinterpret_cast<const float4*>(Ks);
    const float4* V4 = reinterpret_cast<const float4*>(Vs);
    for (int l = 0; l < NL; l++) {
        float4 kv = K4[l];
        float p = __expf(q0 * kv.x + q1 * kv.y + q2 * kv.z + q3 * kv.w);
        float4 vv = V4[l];
        se += p;
        a0 += p * vv.x; a1 += p * vv.y; a2 += p * vv.z; a3 += p * vv.w;
    }
    float inv = 1.f / se;
    float* ob = o + ((long)b * NC + head * 4) * NL;
    ob[row] = a0 * inv;
    ob[NL + row] = a1 * inv;
    ob[2 * NL + row] = a2 * inv;
    ob[3 * NL + row] = a3 * inv;
}

// ---------------- unit: SSD mix A ----------------
__device__ void mixA_unit(float* sm, int u, const float* __restrict__ h,
                          const float* __restrict__ hzw, const float* __restrict__ D,
                          float* __restrict__ ubuf) {
    float* hs = sm;  // 64x64
    int b = u >> 3, o8 = (u & 7) * 8;
    int t = threadIdx.x;
    for (int i = t; i < NC * NS; i += 256) hs[i] = h[(long)b * NC * NS + i];
    __syncthreads();
    float Dv = D[0];
    int s = t & 63, ol = t >> 6;
#pragma unroll
    for (int k = 0; k < 2; k++) {
        int o = o8 + ol * 2 + k;
        const float* w1 = hzw + (long)o * NC;
        const float* w2 = hzw + (long)(NC + o) * NC;
        float a1 = 0.f, a2 = 0.f;
#pragma unroll 4
        for (int c = 0; c < NC; c++) {
            float hv = hs[c * NS + s];
            a1 += w1[c] * hv;
            a2 += w2[c] * hv;
        }
        float sil = a2 / (1.f + __expf(-a2));
        ubuf[((long)b * NC + o) * NS + s] = a1 * sil + a1 * Dv;
    }
}

// ---------------- unit: SSD out (mixB inline + @ cmbuf) ----------------
__device__ void sout_unit(float* sm, int u, const float* __restrict__ ubuf,
                          const float* __restrict__ ow, const float* __restrict__ cmbuf,
                          float* __restrict__ xa) {
    float* us = sm;          // 64x64
    float* hst = sm + 4096;  // [s][16]
    int cg = u & 3, lt = (u >> 2) & 3, b = u >> 4;
    int t = threadIdx.x;
    for (int i = t; i < NC * NS; i += 256) us[i] = ubuf[(long)b * NC * NS + i];
    __syncthreads();
    for (int idx = t; idx < 1024; idx += 256) {
        int oi = idx & 15, s = idx >> 4;
        const float* wr = ow + (long)(cg * 16 + oi) * NC;
        float acc = 0.f;
#pragma unroll 4
        for (int c = 0; c < NC; c++) acc += wr[c] * us[c * NS + s];
        hst[s * 16 + oi] = acc;
    }
    __syncthreads();
    if (t >= 196) return;
    int l = lt * 196 + t;
    const float* Cm = cmbuf + (long)b * NC * NL + l;
    float acc[16];
#pragma unroll
    for (int i = 0; i < 16; i++) acc[i] = 0.f;
#pragma unroll 4
    for (int s = 0; s < NS; s++) {
        float cv = Cm[(long)s * NL];
        const float* hp = hst + s * 16;
#pragma unroll
        for (int i = 0; i < 16; i++) acc[i] += hp[i] * cv;
    }
#pragma unroll
    for (int i = 0; i < 16; i++)
        xa[(long)b * ND * NL + (long)(128 + cg * 16 + i) * NL + l] = acc[i];
}

// ---------------- phase kernels (one unit per block) ----------------
static constexpr int U_DW1 = 512, U_MRA = 512, U_PW13 = 156;  // 12 otiles x 13 pslots
static constexpr int P0_N = U_DW1 + U_MRA + 2 * U_PW13;       // 1336
static constexpr int U_STAR = 104, U_WH = 64, U_ATT = 512, U_CM = 512;
static constexpr int P1_N = U_STAR + U_WH + U_ATT + U_CM;     // 1192
static constexpr int U_PW4 = 52, U_MIXA = 64;
static constexpr int P2_N = 2 * U_PW4 + U_MIXA;               // 168
static constexpr int P3_N = 512 + 128;                        // 640
static constexpr int P4_N = 104;
static constexpr int P5_N = 208;

__global__ void phase0_k(MegaParams p) {
    __shared__ float sm[2528];
    float* scr = g_scr;
    const long XBS = (long)ND * NL;
    const long C64 = (long)NC * NL;
    const long C192 = (long)192 * NL;
    int u = blockIdx.x;
    if (u < U_DW1) {
        dw7_unit(sm, u, p.x, XBS, p.dw1_w, p.dw1_b, p.bn_dw1, scr + O_X1O, C64);
    } else if (u < U_DW1 + U_MRA) {
        mra_unit(sm, u - U_DW1, p.x, p.h1w, p.v1w, p.h2w, p.v2w, p.bn_mra, scr + O_XA);
    } else if (u < U_DW1 + U_MRA + U_PW13) {
        int v = u - U_DW1 - U_MRA;
        pw_unit<64>(sm, v % 12, v / 12, p.x + 128 * NL, XBS, p.bcdt_w, 192,
                    nullptr, nullptr, nullptr, 0, scr + O_BCDT0, C192, M_NONE);
    } else {
        int v = u - U_DW1 - U_MRA - U_PW13;
        pw_unit<64>(sm, v % 12, v / 12, p.x + 192 * NL, XBS, p.qkv_w, 192,
                    nullptr, nullptr, nullptr, 0, scr + O_QKV, C192, M_NONE);
    }
}

__global__ void phase1_k(MegaParams p) {
    __shared__ float sm[6272];
    float* scr = g_scr;
    int u = blockIdx.x;
    if (u < U_STAR) {
        star_unit(sm, u % 8, u / 8, scr + O_X1O, p.f1_w, p.f1_b, p.f2_w, p.f2_b,
                  scr + O_T2);
    } else if (u < U_STAR + U_WH) {
        wh_unit(sm, u - U_STAR, p.x, scr + O_BCDT0, p.ssd_dw, p.A, scr + O_H);
    } else if (u < U_STAR + U_WH + U_ATT) {
        attn_unit(sm, u - U_STAR - U_WH, scr + O_QKV, scr + O_O);
    } else {
        cm_unit(sm, u - U_STAR - U_WH - U_ATT, scr + O_BCDT0, p.ssd_dw, scr + O_CM);
    }
}

__global__ void phase2_k(MegaParams p) {
    __shared__ float sm[4096];
    float* scr = g_scr;
    const long XBS = (long)ND * NL;
    const long C64 = (long)NC * NL;
    const long C128 = (long)NHID * NL;
    int u = blockIdx.x;
    if (u < U_PW4) {
        pw_unit<128>(sm, u % 4, u / 4, scr + O_T2, C128, p.g_w, NC, p.g_b, p.bn_g,
                     nullptr, 0, scr + O_TMP1, C64, M_BN);
    } else if (u < 2 * U_PW4) {
        int v = u - U_PW4;
        pw_unit<64>(sm, v % 4, v / 4, scr + O_O, C64, p.proj_w, NC, nullptr, p.bn_n4,
                    p.x + 192 * NL, XBS, scr + O_XA + 192 * NL, XBS, M_ADD_BN);
    } else {
        mixA_unit(sm, u - 2 * U_PW4, scr + O_H, p.hz_w, p.D, scr + O_U);
    }
}

__global__ void phase3_k(MegaParams p) {
    __shared__ float sm[5120];
    float* scr = g_scr;
    const long XBS = (long)ND * NL;
    const long C64 = (long)NC * NL;
    int u = blockIdx.x;
    if (u < 512) {
        dw7_unit(sm, u, scr + O_TMP1, C64, p.dw2_w, p.dw2_b, nullptr, scr + O_XA, XBS);
    } else {
        sout_unit(sm, u - 512, scr + O_U, p.ow, scr + O_CM, scr + O_XA);
    }
}

__global__ void phase4_k(MegaParams p) {
    __shared__ float sm[4096];
    float* scr = g_scr;
    const long XBS = (long)ND * NL;
    const long C128 = (long)NHID * NL;
    int u = blockIdx.x;
    pw_unit<256>(sm, u % 8, u / 8, scr + O_XA, XBS, p.mlp1_w, NHID, nullptr, p.bn_mlp,
                 nullptr, 0, scr + O_M1, C128, M_BN_RELU);
}

__global__ void phase5_k(MegaParams p) {
    __shared__ float sm[2048];
    float* scr = g_scr;
    const long XBS = (long)ND * NL;
    const long C128 = (long)NHID * NL;
    int u = blockIdx.x;
    pw_unit<128>(sm, u % 16, u / 16, scr + O_M1, C128, p.mlp2_w, ND, nullptr, p.bn_n1,
                 p.x, XBS, p.out, XBS, M_BN_ADD);
}

// ---------------- launch ----------------
extern "C" void kernel_launch(void* const* d_in, const int* in_sizes, int n_in,
                              void* d_out, int out_size) {
    MegaParams p;
    p.x       = (const float*)d_in[0];
    p.dw1_w   = (const float*)d_in[1];
    p.dw1_b   = (const float*)d_in[2];
    p.bn_dw1  = (const float*)d_in[3];
    p.f1_w    = (const float*)d_in[4];
    p.f1_b    = (const float*)d_in[5];
    p.f2_w    = (const float*)d_in[6];
    p.f2_b    = (const float*)d_in[7];
    p.g_w     = (const float*)d_in[8];
    p.g_b     = (const float*)d_in[9];
    p.bn_g    = (const float*)d_in[10];
    p.dw2_w   = (const float*)d_in[11];
    p.dw2_b   = (const float*)d_in[12];
    p.h1w     = (const float*)d_in[13];
    p.v1w     = (const float*)d_in[14];
    p.h2w     = (const float*)d_in[15];
    p.v2w     = (const float*)d_in[16];
    p.bn_mra  = (const float*)d_in[17];
    p.bcdt_w  = (const float*)d_in[18];
    p.ssd_dw  = (const float*)d_in[19];
    p.hz_w    = (const float*)d_in[20];
    p.ow      = (const float*)d_in[21];
    p.A       = (const float*)d_in[22];
    p.D       = (const float*)d_in[23];
    p.qkv_w   = (const float*)d_in[24];
    p.proj_w  = (const float*)d_in[25];
    p.bn_n4   = (const float*)d_in[26];
    p.mlp1_w  = (const float*)d_in[27];
    p.bn_mlp  = (const float*)d_in[28];
    p.mlp2_w  = (const float*)d_in[29];
    p.bn_n1   = (const float*)d_in[30];
    p.out     = (float*)d_out;

    phase0_k<<<P0_N, 256>>>(p);
    phase1_k<<<P1_N, 256>>>(p);
    phase2_k<<<P2_N, 256>>>(p);
    phase3_k<<<P3_N, 256>>>(p);
    phase4_k<<<P4_N, 256>>>(p);
    phase5_k<<<P5_N, 256>>>(p);
}

// round 10
// speedup vs baseline: 1.0641x; 1.0641x over previous
#include <cuda_runtime.h>
#include <math.h>

// ---------------- static config ----------------
static constexpr int NB = 8;
static constexpr int ND = 256;
static constexpr int NC = 64;
static constexpr int NHID = 128;
static constexpr int NS = 64;
static constexpr int NHH = 28, NWW = 28;
static constexpr int NL = NHH * NWW;        // 784
static constexpr int NHEAD = 16;
static constexpr int NPAIRS = NB * NL / 2;  // 3136
static constexpr int PPB = NL / 2;          // 392

typedef unsigned long long ull;

// ---------------- packed f32x2 helpers ----------------
__device__ __forceinline__ ull pk2(float lo, float hi) {
    ull r;
    asm("mov.b64 %0, {%1, %2};" : "=l"(r) : "f"(lo), "f"(hi));
    return r;
}
__device__ __forceinline__ float2 upk2(ull v) {
    float2 r;
    asm("mov.b64 {%0, %1}, %2;" : "=f"(r.x), "=f"(r.y) : "l"(v));
    return r;
}
__device__ __forceinline__ ull ffma2(ull a, ull b, ull c) {
    ull d;
    asm("fma.rn.f32x2 %0, %1, %2, %3;" : "=l"(d) : "l"(a), "l"(b), "l"(c));
    return d;
}

// ---------------- scratch arena ----------------
static constexpr long O_X1O   = 0;                          // (8,64,784)
static constexpr long O_T2    = O_X1O   + (long)NB*NC*NL;   // (8,128,784)
static constexpr long O_TMP1  = O_T2    + (long)NB*NHID*NL; // (8,64,784)
static constexpr long O_BCDT0 = O_TMP1  + (long)NB*NC*NL;   // (8,192,784)
static constexpr long O_CM    = O_BCDT0 + (long)NB*192*NL;  // (8,64,784)
static constexpr long O_H     = O_CM    + (long)NB*NC*NL;   // (8,64,64)
static constexpr long O_U     = O_H     + (long)NB*NC*NS;   // (8,64,64)
static constexpr long O_QKV   = O_U     + (long)NB*NC*NS;   // (8,192,784)
static constexpr long O_O     = O_QKV   + (long)NB*192*NL;  // (8,64,784)
static constexpr long O_XA    = O_O     + (long)NB*NC*NL;   // (8,256,784)
static constexpr long O_M1    = O_XA    + (long)NB*ND*NL;   // (8,128,784)
static constexpr long SCR_TOTAL = O_M1 + (long)NB*NHID*NL;

__device__ __align__(16) float g_scr[SCR_TOTAL];

enum { M_NONE = 0, M_ADD_BN, M_BN_RELU, M_BN_ADD, M_BN };

// ---------------- pointwise conv (f32x2 packed), pixel-pair tiled ----------------
template <int CIN>
__global__ void pwconv_k(const float* __restrict__ in, long ibs,
                         const float* __restrict__ w, int cout,
                         const float* __restrict__ bias,
                         const float* __restrict__ bnp,
                         const float* __restrict__ res, long rbs,
                         float* __restrict__ out, long obs, int mode) {
    constexpr int OT = 16;
    __shared__ __align__(16) float ws[CIN * OT];  // transposed: ws[c*16+i]
    int obase = blockIdx.x * OT;
    for (int idx = threadIdx.x; idx < CIN * OT; idx += 128) {
        int c = idx >> 4, i = idx & 15;
        ws[idx] = w[(long)(obase + i) * CIN + c];
    }
    __syncthreads();
    int pp = blockIdx.y * 128 + threadIdx.x;
    if (pp >= NPAIRS) return;
    int b = pp / PPB;
    int l = (pp % PPB) * 2;
    const float2* ip2 = reinterpret_cast<const float2*>(in + (long)b * ibs + l);

    ull acc0[8], acc1[8];  // output-pairs (2j,2j+1) for pixel0 / pixel1
#pragma unroll
    for (int j = 0; j < 8; j++) { acc0[j] = 0ull; acc1[j] = 0ull; }
#pragma unroll 4
    for (int c = 0; c < CIN; c++) {
        float2 xv = ip2[c * (NL / 2)];
        ull x0 = pk2(xv.x, xv.x);
        ull x1 = pk2(xv.y, xv.y);
        const ull* wp = reinterpret_cast<const ull*>(ws + c * OT);
#pragma unroll
        for (int j = 0; j < 8; j++) {
            ull wv = wp[j];
            acc0[j] = ffma2(wv, x0, acc0[j]);
            acc1[j] = ffma2(wv, x1, acc1[j]);
        }
    }
#pragma unroll
    for (int j = 0; j < 8; j++) {
        float2 e0 = upk2(acc0[j]);
        float2 e1 = upk2(acc1[j]);
#pragma unroll
        for (int k = 0; k < 2; k++) {
            int o = obase + 2 * j + k;
            float s0 = (k == 0) ? e0.x : e0.y;
            float s1 = (k == 0) ? e1.x : e1.y;
            if (bias) { s0 += bias[o]; s1 += bias[o]; }
            if (mode >= M_ADD_BN) {
                long roff = (long)b * rbs + (long)o * NL + l;
                if (mode == M_ADD_BN) {
                    float2 rv = *reinterpret_cast<const float2*>(res + roff);
                    s0 += rv.x; s1 += rv.y;
                }
                float g = bnp[o], be = bnp[cout + o], mm = bnp[2 * cout + o],
                      vv = bnp[3 * cout + o];
                float sc = g * rsqrtf(vv + 1e-5f);
                s0 = (s0 - mm) * sc + be;
                s1 = (s1 - mm) * sc + be;
                if (mode == M_BN_RELU) { s0 = fmaxf(s0, 0.f); s1 = fmaxf(s1, 0.f); }
                if (mode == M_BN_ADD) {
                    float2 rv = *reinterpret_cast<const float2*>(res + roff);
                    s0 += rv.x; s1 += rv.y;
                }
            }
            *reinterpret_cast<float2*>(out + (long)b * obs + (long)o * NL + l) =
                make_float2(s0, s1);
        }
    }
}

// ---------------- fused star MLP (f32x2 packed) ----------------
__global__ void star_k(const float* __restrict__ in,
                       const float* __restrict__ w1, const float* __restrict__ b1,
                       const float* __restrict__ w2, const float* __restrict__ b2,
                       float* __restrict__ out) {
    constexpr int OT = 16, CIN = NC;
    __shared__ __align__(16) float ws1[CIN * OT];
    __shared__ __align__(16) float ws2[CIN * OT];
    int obase = blockIdx.x * OT;
    for (int idx = threadIdx.x; idx < CIN * OT; idx += 128) {
        int c = idx >> 4, i = idx & 15;
        ws1[idx] = w1[(long)(obase + i) * CIN + c];
        ws2[idx] = w2[(long)(obase + i) * CIN + c];
    }
    __syncthreads();
    int pp = blockIdx.y * 128 + threadIdx.x;
    if (pp >= NPAIRS) return;
    int b = pp / PPB;
    int l = (pp % PPB) * 2;
    const float2* ip2 = reinterpret_cast<const float2*>(in + (long)b * NC * NL + l);

    ull p0[8], p1[8], q0[8], q1[8];
#pragma unroll
    for (int j = 0; j < 8; j++) { p0[j] = p1[j] = q0[j] = q1[j] = 0ull; }
#pragma unroll 4
    for (int c = 0; c < CIN; c++) {
        float2 xv = ip2[c * (NL / 2)];
        ull x0 = pk2(xv.x, xv.x);
        ull x1 = pk2(xv.y, xv.y);
        const ull* w1p = reinterpret_cast<const ull*>(ws1 + c * OT);
        const ull* w2p = reinterpret_cast<const ull*>(ws2 + c * OT);
#pragma unroll
        for (int j = 0; j < 8; j++) {
            ull w1v = w1p[j], w2v = w2p[j];
            p0[j] = ffma2(w1v, x0, p0[j]);
            p1[j] = ffma2(w1v, x1, p1[j]);
            q0[j] = ffma2(w2v, x0, q0[j]);
            q1[j] = ffma2(w2v, x1, q1[j]);
        }
    }
#pragma unroll
    for (int j = 0; j < 8; j++) {
        float2 ep0 = upk2(p0[j]), ep1 = upk2(p1[j]);
        float2 eq0 = upk2(q0[j]), eq1 = upk2(q1[j]);
#pragma unroll
        for (int k = 0; k < 2; k++) {
            int o = obase + 2 * j + k;
            float pa = (k == 0) ? ep0.x : ep0.y;
            float pb = (k == 0) ? ep1.x : ep1.y;
            float qa = (k == 0) ? eq0.x : eq0.y;
            float qb = (k == 0) ? eq1.x : eq1.y;
            float h0 = fminf(fmaxf(pa + b1[o], 0.f), 6.f);
            float h1 = fminf(fmaxf(pb + b1[o], 0.f), 6.f);
            *reinterpret_cast<float2*>(out + ((long)b * NHID + o) * NL + l) =
                make_float2(h0 * (qa + b2[o]), h1 * (qb + b2[o]));
        }
    }
}

// ---------------- depthwise 7x7: 2 px/thread ----------------
__global__ void dw7x7_k(const float* __restrict__ in, long ibs,
                        const float* __restrict__ w, const float* __restrict__ bias,
                        const float* __restrict__ bnp,
                        float* __restrict__ out, long obs) {
    int bc = blockIdx.x;
    int c = bc % NC, b = bc / NC;
    const float* ip = in + (long)b * ibs + (long)c * NL;
    __shared__ float pl[34 * 34];
    __shared__ float wsh[49];
    int t = threadIdx.x;  // 392
    for (int i = t; i < 34 * 34; i += 392) pl[i] = 0.f;
    if (t < 49) wsh[t] = w[c * 49 + t];
    __syncthreads();
    {
        int l = t * 2;
        int y = l / NWW, x = l % NWW;
        float2 v = *reinterpret_cast<const float2*>(ip + l);
        pl[(y + 3) * 34 + x + 3] = v.x;
        pl[(y + 3) * 34 + x + 4] = v.y;
    }
    __syncthreads();
    float sc = 1.f, sh = 0.f;
    if (bnp) {
        float g = bnp[c], be = bnp[NC + c], mm = bnp[2 * NC + c], vv = bnp[3 * NC + c];
        sc = g * rsqrtf(vv + 1e-5f);
        sh = be - mm * sc;
    }
    float bi = bias[c];
    int y = t / 14, x0 = (t % 14) * 2;
    float s0 = 0.f, s1 = 0.f;
#pragma unroll
    for (int ky = 0; ky < 7; ky++) {
        float r[8];
        const float* row = pl + (y + ky) * 34 + x0;
#pragma unroll
        for (int kx = 0; kx < 8; kx++) r[kx] = row[kx];
#pragma unroll
        for (int kx = 0; kx < 7; kx++) {
            float wv = wsh[ky * 7 + kx];
            s0 += wv * r[kx];
            s1 += wv * r[kx + 1];
        }
    }
    s0 = (s0 + bi) * sc + sh;
    s1 = (s1 + bi) * sc + sh;
    *reinterpret_cast<float2*>(out + (long)b * obs + (long)c * NL + y * NWW + x0) =
        make_float2(s0, s1);
}

// ---------------- branch 2 fully fused ----------------
__global__ void mra_branch_k(const float* __restrict__ x,
                             const float* __restrict__ h1w, const float* __restrict__ v1w,
                             const float* __restrict__ h2w, const float* __restrict__ v2w,
                             const float* __restrict__ bnp, float* __restrict__ xa) {
    int bc = blockIdx.x;
    int c = bc % NC, b = bc / NC;
    const float* ip = x + ((long)b * ND + NC + c) * NL;
    __shared__ float xp[NL], mp[NL];
    __shared__ float xs[100], ht[190], vt[190], c2[190], c2v[190], att_s[100];
    int t = threadIdx.x;  // 196
    for (int i = t; i < NL; i += 196) xp[i] = ip[i];
    __syncthreads();
    for (int i = t; i < NL; i += 196) {
        int y = i / NWW, xx = i % NWW;
        float mx = -1e30f;
        for (int dy = -1; dy <= 1; dy++) {
            int yy = y + dy;
            if (yy < 0 || yy >= NHH) continue;
            for (int dx = -1; dx <= 1; dx++) {
                int xxx = xx + dx;
                if (xxx < 0 || xxx >= NWW) continue;
                mx = fmaxf(mx, xp[yy * NWW + xxx]);
            }
        }
        mp[i] = mx;
    }
    __syncthreads();
    if (t < 100) {
        int i = t / 10, j = t % 10;
        const float filt[4] = {1.f, 3.f, 3.f, 1.f};
        float s = 0.f;
        for (int fy = 0; fy < 4; fy++) {
            int oy = 3 * i + fy - 1;
            if (oy < 0) oy = -oy;
            if (oy >= NHH) oy = 2 * NHH - 2 - oy;
            for (int fx = 0; fx < 4; fx++) {
                int ox = 3 * j + fx - 1;
                if (ox < 0) ox = -ox;
                if (ox >= NWW) ox = 2 * NWW - 2 - ox;
                s += filt[fy] * filt[fx] * mp[oy * NWW + ox];
            }
        }
        xs[t] = s * (1.f / 64.f);
    }
    __syncthreads();
    if (t < 190) {
        {
            int row = t / 20, col = t % 20;
            ht[t] = (col < 10) ? xs[row * 10 + col] : 0.f;
        }
        {
            int a = t / 10, b2 = t % 10;
            int k = b2 * 19 + a, row = k / 20, col = k % 20;
            vt[t] = (col < 10) ? xs[col * 10 + row] : 0.f;
        }
    }
    __syncthreads();
    if (t < 190) {
        {
            int r = t / 19, j = t % 19;
            float s = 0.f;
            for (int ky = 0; ky < 11; ky++) {
                int yy = r + ky - 5;
                if (yy < 0 || yy >= 10) continue;
                for (int kx = 0; kx < 3; kx++) {
                    int xx = j + kx - 1;
                    if (xx < 0 || xx >= 19) continue;
                    s += h2w[c * 33 + ky * 3 + kx] * ht[yy * 19 + xx];
                }
            }
            c2[t] = s;
        }
        {
            int y = t / 10, x2 = t % 10;
            float s = 0.f;
            for (int ky = 0; ky < 3; ky++) {
                int yy = y + ky - 1;
                if (yy < 0 || yy >= 19) continue;
                for (int kx = 0; kx < 11; kx++) {
                    int xx = x2 + kx - 5;
                    if (xx < 0 || xx >= 10) continue;
                    s += v2w[c * 33 + ky * 11 + kx] * vt[yy * 10 + xx];
                }
            }
            c2v[t] = s;
        }
    }
    __syncthreads();
    if (t < 100) {
        int y = t / 10, xx = t % 10;
        float s = 0.f;
        for (int ky = 0; ky < 11; ky++) {
            int yy = y + ky - 5;
            if (yy < 0 || yy >= 10) continue;
            for (int kx = 0; kx < 3; kx++) {
                int xxx = xx + kx - 1;
                if (xxx < 0 || xxx >= 10) continue;
                s += h1w[c * 33 + ky * 3 + kx] * xs[yy * 10 + xxx];
            }
        }
        for (int ky = 0; ky < 3; ky++) {
            int yy = y + ky - 1;
            if (yy < 0 || yy >= 10) continue;
            for (int kx = 0; kx < 11; kx++) {
                int xxx = xx + kx - 5;
                if (xxx < 0 || xxx >= 10) continue;
                s += v1w[c * 33 + ky * 11 + kx] * xs[yy * 10 + xxx];
            }
        }
        s += c2[y * 20 + xx];
        int k4 = xx * 20 + y;
        s += c2v[(k4 % 19) * 10 + (k4 / 19)];
        float g = bnp[c], be = bnp[NC + c], mm = bnp[2 * NC + c], vv = bnp[3 * NC + c];
        float sc = g * rsqrtf(vv + 1e-5f);
        s = (s - mm) * sc + be;
        att_s[t] = 1.f / (1.f + __expf(-s));
    }
    __syncthreads();
    float* op = xa + (long)b * ND * NL + (long)(NC + c) * NL;
    for (int i = t; i < NL; i += 196) {
        int y = i / NWW, xx = i % NWW;
        op[i] = xp[i] * att_s[((y * 10) / NHH) * 10 + (xx * 10) / NWW];
    }
}

// ---------------- SSD: dw3x3(dt,Bm) inline + softmax + h-GEMM ----------------
__global__ void ssd_wh_k(const float* __restrict__ x, const float* __restrict__ bcdt0,
                         const float* __restrict__ dw, const float* __restrict__ A_param,
                         float* __restrict__ h) {
    __shared__ float Wsh[8 * NL];
    int stile = blockIdx.x & 7, b = blockIdx.x >> 3;
    int warp = threadIdx.x / 32, lane = threadIdx.x % 32;
    {
        int s = stile * 8 + warp;
        float wd[9], wb[9];
#pragma unroll
        for (int k = 0; k < 9; k++) {
            wd[k] = dw[(128 + s) * 9 + k];
            wb[k] = dw[s * 9 + k];
        }
        const float* dtp = bcdt0 + ((long)b * 192 + 128 + s) * NL;
        const float* bmp = bcdt0 + ((long)b * 192 + s) * NL;
        float ap = A_param[s];
        float mx = -1e30f;
        for (int l = lane; l < NL; l += 32) {
            int y = l / NWW, xx = l % NWW;
            float v = 0.f;
#pragma unroll
            for (int ky = 0; ky < 3; ky++) {
                int yy = y + ky - 1;
                if (yy < 0 || yy >= NHH) continue;
#pragma unroll
                for (int kx = 0; kx < 3; kx++) {
                    int xxx = xx + kx - 1;
                    if (xxx < 0 || xxx >= NWW) continue;
                    v += wd[ky * 3 + kx] * dtp[yy * NWW + xxx];
                }
            }
            v += ap;
            Wsh[warp * NL + l] = v;
            mx = fmaxf(mx, v);
        }
#pragma unroll
        for (int o = 16; o > 0; o >>= 1)
            mx = fmaxf(mx, __shfl_xor_sync(0xffffffff, mx, o));
        float sum = 0.f;
        for (int l = lane; l < NL; l += 32) {
            float e = __expf(Wsh[warp * NL + l] - mx);
            Wsh[warp * NL + l] = e;
            sum += e;
        }
#pragma unroll
        for (int o = 16; o > 0; o >>= 1)
            sum += __shfl_xor_sync(0xffffffff, sum, o);
        float inv = 1.f / sum;
        for (int l = lane; l < NL; l += 32) {
            int y = l / NWW, xx = l % NWW;
            float v = 0.f;
#pragma unroll
            for (int ky = 0; ky < 3; ky++) {
                int yy = y + ky - 1;
                if (yy < 0 || yy >= NHH) continue;
#pragma unroll
                for (int kx = 0; kx < 3; kx++) {
                    int xxx = xx + kx - 1;
                    if (xxx < 0 || xxx >= NWW) continue;
                    v += wb[ky * 3 + kx] * bmp[yy * NWW + xxx];
                }
            }
            Wsh[warp * NL + l] *= inv * v;
        }
    }
    __syncthreads();
    for (int i = 0; i < 8; i++) {
        int c = i * 8 + warp;
        const float* xsrc = x + ((long)b * ND + 128 + c) * NL;
        float acc[8];
#pragma unroll
        for (int k = 0; k < 8; k++) acc[k] = 0.f;
        for (int l = lane; l < NL; l += 32) {
            float xv = xsrc[l];
#pragma unroll
            for (int k = 0; k < 8; k++) acc[k] += xv * Wsh[k * NL + l];
        }
#pragma unroll
        for (int k = 0; k < 8; k++) {
#pragma unroll
            for (int o = 16; o > 0; o >>= 1)
                acc[k] += __shfl_down_sync(0xffffffff, acc[k], o);
        }
        if (lane == 0) {
#pragma unroll
            for (int k = 0; k < 8; k++)
                h[((long)b * NC + c) * NS + stile * 8 + k] = acc[k];
        }
    }
}

// ---------------- SSD: dw3x3 of Cm -> cmbuf ----------------
__global__ void ssd_cm_k(const float* __restrict__ bcdt0, const float* __restrict__ dw,
                         float* __restrict__ cmbuf) {
    __shared__ float pl[900];
    __shared__ float wsh[9];
    int s = blockIdx.x & 63, b = blockIdx.x >> 6;
    const float* ip = bcdt0 + ((long)b * 192 + 64 + s) * NL;
    int t = threadIdx.x;
    for (int i = t; i < 900; i += 256) pl[i] = 0.f;
    if (t < 9) wsh[t] = dw[(64 + s) * 9 + t];
    __syncthreads();
    for (int i = t; i < NL; i += 256) {
        int y = i / NWW, x = i % NWW;
        pl[(y + 1) * 30 + x + 1] = ip[i];
    }
    __syncthreads();
    for (int i = t; i < NL; i += 256) {
        int y = i / NWW, x = i % NWW;
        float v = 0.f;
#pragma unroll
        for (int ky = 0; ky < 3; ky++)
#pragma unroll
            for (int kx = 0; kx < 3; kx++)
                v += wsh[ky * 3 + kx] * pl[(y + ky) * 30 + x + kx];
        cmbuf[((long)b * NC + s) * NL + i] = v;
    }
}

// ---------------- SSD mix A ----------------
__global__ void ssd_mixA_k(const float* __restrict__ h, const float* __restrict__ hzw,
                           const float* __restrict__ D, float* __restrict__ ubuf) {
    __shared__ float hs[NC * NS];
    int b = blockIdx.x >> 3, o8 = (blockIdx.x & 7) * 8;
    int t = threadIdx.x;
    for (int i = t; i < NC * NS; i += 256) hs[i] = h[(long)b * NC * NS + i];
    __syncthreads();
    float Dv = D[0];
    int s = t & 63, ol = t >> 6;
#pragma unroll
    for (int k = 0; k < 2; k++) {
        int o = o8 + ol * 2 + k;
        const float* w1 = hzw + (long)o * NC;
        const float* w2 = hzw + (long)(NC + o) * NC;
        float a1 = 0.f, a2 = 0.f;
#pragma unroll 4
        for (int c = 0; c < NC; c++) {
            float hv = hs[c * NS + s];
            a1 += w1[c] * hv;
            a2 += w2[c] * hv;
        }
        float sil = a2 / (1.f + __expf(-a2));
        ubuf[((long)b * NC + o) * NS + s] = a1 * sil + a1 * Dv;
    }
}

// ---------------- SSD out (mixB inline + @ cmbuf) ----------------
__global__ void ssd_out_k(const float* __restrict__ ubuf, const float* __restrict__ ow,
                          const float* __restrict__ cmbuf, float* __restrict__ xa) {
    __shared__ float us[NC * NS];
    __shared__ float hst[NS * 16];
    int cg = blockIdx.x & 3, lt = (blockIdx.x >> 2) & 3, b = blockIdx.x >> 4;
    int t = threadIdx.x;
    for (int i = t; i < NC * NS; i += 256) us[i] = ubuf[(long)b * NC * NS + i];
    __syncthreads();
    for (int idx = t; idx < 1024; idx += 256) {
        int oi = idx & 15, s = idx >> 4;
        const float* wr = ow + (long)(cg * 16 + oi) * NC;
        float acc = 0.f;
#pragma unroll 4
        for (int c = 0; c < NC; c++) acc += wr[c] * us[c * NS + s];
        hst[s * 16 + oi] = acc;
    }
    __syncthreads();
    if (t >= 196) return;
    int l = lt * 196 + t;
    const float* Cm = cmbuf + (long)b * NC * NL + l;
    float acc[16];
#pragma unroll
    for (int i = 0; i < 16; i++) acc[i] = 0.f;
#pragma unroll 4
    for (int s = 0; s < NS; s++) {
        float cv = Cm[(long)s * NL];
        const float* hp = hst + s * 16;
#pragma unroll
        for (int i = 0; i < 16; i++) acc[i] += hp[i] * cv;
    }
#pragma unroll
    for (int i = 0; i < 16; i++)
        xa[(long)b * ND * NL + (long)(128 + cg * 16 + i) * NL + l] = acc[i];
}

// ---------------- GA attention (f32x2 packed) ----------------
__global__ void attn_k(const float* __restrict__ qkv, float* __restrict__ o) {
    int blk = blockIdx.x;
    int rc = blk % 7;
    int bh = blk / 7;
    int head = bh % NHEAD, b = bh / NHEAD;
    __shared__ __align__(16) float Ks[NL * 4];
    __shared__ __align__(16) float Vs[NL * 4];
    const float* kbase = qkv + ((long)b * 192 + 64 + head * 4) * NL;
    const float* vbase = qkv + ((long)b * 192 + 128 + head * 4) * NL;
    for (int i = threadIdx.x; i < NL * 4; i += blockDim.x) {
        int d = i / NL, l = i % NL;
        Ks[l * 4 + d] = kbase[i];
        Vs[l * 4 + d] = vbase[i];
    }
    __syncthreads();
    int row = rc * 128 + threadIdx.x;
    if (row >= NL) return;
    const float* qb = qkv + ((long)b * 192 + head * 4) * NL;
    ull q01 = pk2(qb[row] * 0.5f, qb[NL + row] * 0.5f);
    ull q23 = pk2(qb[2 * NL + row] * 0.5f, qb[3 * NL + row] * 0.5f);
    float se = 0.f;
    ull a01 = 0ull, a23 = 0ull;
    const ulonglong2* K2 = reinterpret_cast<const ulonglong2*>(Ks);
    const ulonglong2* V2 = reinterpret_cast<const ulonglong2*>(Vs);
    for (int l = 0; l < NL; l++) {
        ulonglong2 kv = K2[l];
        ull tdot = ffma2(q01, kv.x, ffma2(q23, kv.y, 0ull));
        float2 td = upk2(tdot);
        float p = __expf(td.x + td.y);
        ulonglong2 vv = V2[l];
        ull pp = pk2(p, p);
        se += p;
        a01 = ffma2(pp, vv.x, a01);
        a23 = ffma2(pp, vv.y, a23);
    }
    float inv = 1.f / se;
    float2 e01 = upk2(a01);
    float2 e23 = upk2(a23);
    float* ob = o + ((long)b * NC + head * 4) * NL;
    ob[row] = e01.x * inv;
    ob[NL + row] = e01.y * inv;
    ob[2 * NL + row] = e23.x * inv;
    ob[3 * NL + row] = e23.y * inv;
}

// ---------------- launch (fork-join across 4 streams) ----------------
extern "C" void kernel_launch(void* const* d_in, const int* in_sizes, int n_in,
                              void* d_out, int out_size) {
    const float* x       = (const float*)d_in[0];
    const float* dw1_w   = (const float*)d_in[1];
    const float* dw1_b   = (const float*)d_in[2];
    const float* bn_dw1  = (const float*)d_in[3];
    const float* f1_w    = (const float*)d_in[4];
    const float* f1_b    = (const float*)d_in[5];
    const float* f2_w    = (const float*)d_in[6];
    const float* f2_b    = (const float*)d_in[7];
    const float* g_w     = (const float*)d_in[8];
    const float* g_b     = (const float*)d_in[9];
    const float* bn_g    = (const float*)d_in[10];
    const float* dw2_w   = (const float*)d_in[11];
    const float* dw2_b   = (const float*)d_in[12];
    const float* hatt1_w = (const float*)d_in[13];
    const float* vatt1_w = (const float*)d_in[14];
    const float* hatt2_w = (const float*)d_in[15];
    const float* vatt2_w = (const float*)d_in[16];
    const float* bn_mra  = (const float*)d_in[17];
    const float* bcdt_w  = (const float*)d_in[18];
    const float* ssd_dw  = (const float*)d_in[19];
    const float* hz_w    = (const float*)d_in[20];
    const float* out_w   = (const float*)d_in[21];
    const float* A_param = (const float*)d_in[22];
    const float* D_param = (const float*)d_in[23];
    const float* qkv_w   = (const float*)d_in[24];
    const float* proj_w  = (const float*)d_in[25];
    const float* bn_n4   = (const float*)d_in[26];
    const float* mlp1_w  = (const float*)d_in[27];
    const float* bn_mlp  = (const float*)d_in[28];
    const float* mlp2_w  = (const float*)d_in[29];
    const float* bn_n1   = (const float*)d_in[30];
    float* out = (float*)d_out;

    float* scr = nullptr;
    cudaGetSymbolAddress((void**)&scr, g_scr);
    float* x1o   = scr + O_X1O;
    float* t2    = scr + O_T2;
    float* tmp1  = scr + O_TMP1;
    float* bcdt0 = scr + O_BCDT0;
    float* cmbuf = scr + O_CM;
    float* hbuf  = scr + O_H;
    float* ubuf  = scr + O_U;
    float* qkv   = scr + O_QKV;
    float* obuf  = scr + O_O;
    float* xa    = scr + O_XA;
    float* m1    = scr + O_M1;

    const long XBS = (long)ND * NL;
    const long C64 = (long)NC * NL;
    const long C128 = (long)NHID * NL;
    const long C192 = (long)192 * NL;
    const int PT = (NPAIRS + 127) / 128;

    static cudaStream_t s1 = nullptr, s2 = nullptr, s3 = nullptr;
    static cudaEvent_t eFork, eJ1, eJ2, eJ3;
    if (!s1) {
        cudaStreamCreateWithFlags(&s1, cudaStreamNonBlocking);
        cudaStreamCreateWithFlags(&s2, cudaStreamNonBlocking);
        cudaStreamCreateWithFlags(&s3, cudaStreamNonBlocking);
        cudaEventCreateWithFlags(&eFork, cudaEventDisableTiming);
        cudaEventCreateWithFlags(&eJ1, cudaEventDisableTiming);
        cudaEventCreateWithFlags(&eJ2, cudaEventDisableTiming);
        cudaEventCreateWithFlags(&eJ3, cudaEventDisableTiming);
    }

    cudaEventRecord(eFork, 0);
    cudaStreamWaitEvent(s1, eFork, 0);
    cudaStreamWaitEvent(s2, eFork, 0);
    cudaStreamWaitEvent(s3, eFork, 0);

    // ---- branch 2 (s1) ----
    mra_branch_k<<<NB * NC, 196, 0, s1>>>(x, hatt1_w, vatt1_w, hatt2_w, vatt2_w,
                                          bn_mra, xa);
    cudaEventRecord(eJ1, s1);

    // ---- branch 3 (s2) ----
    pwconv_k<64><<<dim3(192 / 16, PT), 128, 0, s2>>>(x + 128 * NL, XBS, bcdt_w, 192,
                                                     nullptr, nullptr, nullptr, 0,
                                                     bcdt0, C192, M_NONE);
    ssd_cm_k<<<NB * NC, 256, 0, s2>>>(bcdt0, ssd_dw, cmbuf);
    ssd_wh_k<<<NB * 8, 256, 0, s2>>>(x, bcdt0, ssd_dw, A_param, hbuf);
    ssd_mixA_k<<<NB * 8, 256, 0, s2>>>(hbuf, hz_w, D_param, ubuf);
    ssd_out_k<<<NB * 16, 256, 0, s2>>>(ubuf, out_w, cmbuf, xa);
    cudaEventRecord(eJ2, s2);

    // ---- branch 4 (s3) ----
    pwconv_k<64><<<dim3(192 / 16, PT), 128, 0, s3>>>(x + 192 * NL, XBS, qkv_w, 192,
                                                     nullptr, nullptr, nullptr, 0,
                                                     qkv, C192, M_NONE);
    attn_k<<<NB * NHEAD * 7, 128, 0, s3>>>(qkv, obuf);
    pwconv_k<64><<<dim3(NC / 16, PT), 128, 0, s3>>>(obuf, C64, proj_w, NC, nullptr,
                                                    bn_n4, x + 192 * NL, XBS,
                                                    xa + 192 * NL, XBS, M_ADD_BN);
    cudaEventRecord(eJ3, s3);

    // ---- branch 1 (default stream) ----
    dw7x7_k<<<NB * NC, 392>>>(x, XBS, dw1_w, dw1_b, bn_dw1, x1o, C64);
    star_k<<<dim3(NHID / 16, PT), 128>>>(x1o, f1_w, f1_b, f2_w, f2_b, t2);
    pwconv_k<128><<<dim3(NC / 16, PT), 128>>>(t2, C128, g_w, NC, g_b, bn_g,
                                              nullptr, 0, tmp1, C64, M_BN);
    dw7x7_k<<<NB * NC, 392>>>(tmp1, C64, dw2_w, dw2_b, nullptr, xa, XBS);

    // ---- join ----
    cudaStreamWaitEvent(0, eJ1, 0);
    cudaStreamWaitEvent(0, eJ2, 0);
    cudaStreamWaitEvent(0, eJ3, 0);

    // ---- merge MLP + residual ----
    pwconv_k<256><<<dim3(NHID / 16, PT), 128>>>(xa, XBS, mlp1_w, NHID, nullptr, bn_mlp,
                                                nullptr, 0, m1, C128, M_BN_RELU);
    pwconv_k<128><<<dim3(ND / 16, PT), 128>>>(m1, C128, mlp2_w, ND, nullptr, bn_n1,
                                              x, XBS, out, XBS, M_BN_ADD);
}